// round 14
// baseline (speedup 1.0000x reference)
#include <cuda_runtime.h>
#include <cstdint>

// Problem constants
#define BB 8            // clouds
#define NN 4096         // points per cloud
#define M1 1024         // ceil(0.25*4096) base fps picks per cloud
#define M2 820          // ceil(0.20*4096) extra fps picks per cloud
#define OVSZ 1638       // int(8*1024*0.2) : extra picks kept
#define MTOT 9830       // BB*M1 + OVSZ
#define KNN 16

#define FPS_T 256
#define PPT 16          // points per thread (contiguous)
#define PAIRS 8

typedef unsigned long long u64;

// Internal int-valued combined indices (kNN consumes these; d_out is float32).
__device__ int g_cidx[MTOT];

// Packed f32x2 helpers (two rn.f32 ops in one instruction, bit-identical)
#define ADD2(out, a, b) asm("add.rn.f32x2 %0, %1, %2;" : "=l"(out) : "l"(a), "l"(b))
#define MUL2(out, a, b) asm("mul.rn.f32x2 %0, %1, %2;" : "=l"(out) : "l"(a), "l"(b))
#define PACK2(out, lo, hi) asm("mov.b64 %0, {%1, %2};" : "=l"(out) : "r"(lo), "r"(hi))
#define UNPK2(lo, hi, in)  asm("mov.b64 {%0, %1}, %2;" : "=r"(lo), "=r"(hi) : "l"(in))

// -------------------------------------------------------------------------
// FPS: one block per cloud, 256 threads, contiguous 16 points/thread in
// registers; winner coords from a 64KB smem float4 mirror (broadcast
// LDS.128). NEW single-atomic reduction tail:
//   - per-thread argmax (ascending scan, strict > -> smallest-idx ties)
//   - warp REDUX max (filter); every lane with bv==wmax fires ONE
//     atomicMax(u64) on a single slot with key (dist<<32)|(NN-1-idx).
//     max(key) == max dist with min-index tie-break == jnp.argmax exactly.
//     No ballot, no slot array, no block-scan stage.
//   - ONE barrier (drains the ~1-2 atoms/warp); then one broadcast LDS.64
//     -> winner; coords via LDS.128.
//   - slot triple-buffered on s%3; t0 resets buffer (s+1)%3 pre-barrier
//     (its last readers finished two barriers ago -> race-free).
// t==0 records winners in smem; all g_cidx/outf stores flushed at the end.
// m2 extra-fps picks are a prefix of the m1 sequence -> one pass emits all.
// -------------------------------------------------------------------------
extern __shared__ float4 scoords[];      // [NN] = 64KB dynamic

__global__ void __launch_bounds__(FPS_T, 1)
fps_kernel(const float* __restrict__ pos, float* __restrict__ outf)
{
    __shared__ alignas(16) u64 slot[3];  // triple-buffered argmax accumulator
    __shared__ int swin[M1];             // winner history (local indices)

    const int b    = blockIdx.x;
    const int t    = threadIdx.x;
    const unsigned full = 0xffffffffu;

    const float* __restrict__ p = pos + (size_t)b * NN * 3;
    const int base = t * PPT;            // contiguous ownership

    u64 rx2[PAIRS], ry2[PAIRS], rz2[PAIRS];
    float mind[PPT];
#pragma unroll
    for (int m = 0; m < PAIRS; ++m) {
        int i0 = base + 2 * m;
        float x0 = p[3 * i0 + 0], y0 = p[3 * i0 + 1], z0 = p[3 * i0 + 2];
        float x1 = p[3 * i0 + 3], y1 = p[3 * i0 + 4], z1 = p[3 * i0 + 5];
        PACK2(rx2[m], __float_as_uint(x0), __float_as_uint(x1));
        PACK2(ry2[m], __float_as_uint(y0), __float_as_uint(y1));
        PACK2(rz2[m], __float_as_uint(z0), __float_as_uint(z1));
        mind[2 * m]     = __int_as_float(0x7f800000);
        mind[2 * m + 1] = __int_as_float(0x7f800000);
        scoords[i0]     = make_float4(x0, y0, z0, 0.0f);
        scoords[i0 + 1] = make_float4(x1, y1, z1, 0.0f);
    }

    if (t == 0) { swin[0] = 0; slot[0] = 0; slot[1] = 0; slot[2] = 0; }
    __syncthreads();                     // scoords + slots visible

    int last = 0;
    int par  = 1;                        // s % 3, starting at s=1

    for (int s = 1; s < M1; ++s) {
        float4 c = scoords[last];        // ONE broadcast LDS.128
        unsigned nlx = __float_as_uint(-c.x);
        unsigned nly = __float_as_uint(-c.y);
        unsigned nlz = __float_as_uint(-c.z);
        u64 nlx2, nly2, nlz2;
        PACK2(nlx2, nlx, nlx);
        PACK2(nly2, nly, nly);
        PACK2(nlz2, nlz, nlz);

        float bestv = -1.0f;
        int   besti = base;
#pragma unroll
        for (int m = 0; m < PAIRS; ++m) {
            u64 dx2, dy2, dz2, xx2, yy2, zz2, t2, s2;
            ADD2(dx2, rx2[m], nlx2);
            ADD2(dy2, ry2[m], nly2);
            ADD2(dz2, rz2[m], nlz2);
            MUL2(xx2, dx2, dx2);
            MUL2(yy2, dy2, dy2);
            MUL2(zz2, dz2, dz2);
            ADD2(t2, xx2, yy2);
            ADD2(s2, t2, zz2);
            unsigned b0, b1;
            UNPK2(b0, b1, s2);
            float m0 = fminf(mind[2 * m],     __uint_as_float(b0));
            float m1 = fminf(mind[2 * m + 1], __uint_as_float(b1));
            mind[2 * m]     = m0;
            mind[2 * m + 1] = m1;
            // ascending idx + strict > keeps smallest idx on tie
            if (m0 > bestv) { bestv = m0; besti = base + 2 * m;     }
            if (m1 > bestv) { bestv = m1; besti = base + 2 * m + 1; }
        }

        // Warp REDUX filters to the tied lanes; each fires one atomicMax.
        // Packed key makes max() == (max dist, then min idx) exactly.
        unsigned bv   = __float_as_uint(bestv);
        unsigned wmax = __reduce_max_sync(full, bv);
        if (bv == wmax) {
            u64 key = ((u64)wmax << 32) | (unsigned)(NN - 1 - besti);
            atomicMax(&slot[par], key);
        }

        // t0 resets the buffer for step s+1 (last read 2 barriers ago).
        int parNext = par + 1; if (parNext == 3) parNext = 0;
        if (t == 0) slot[parNext] = 0;

        __syncthreads();                 // atoms drained; slot[par] final

        u64 k = slot[par];               // broadcast LDS.64
        int win = NN - 1 - (int)(unsigned)(k & 0xffffffffu);

        if (t == 0) swin[s] = win;       // 1 STS; no global stores here
        last = win;
        par  = parNext;
    }

    // Cooperative flush: all picks -> g_cidx + outf (base + extra regions).
    __syncthreads();
    for (int s = t; s < M1; s += FPS_T) {
        int g = b * NN + swin[s];
        float gf = (float)g;
        g_cidx[b * M1 + s] = g;  outf[b * M1 + s] = gf;
        if (b == 0 && s < M2) {
            g_cidx[BB * M1 + s] = g;  outf[BB * M1 + s] = gf;
        }
        if (b == 1 && s < (OVSZ - M2)) {
            g_cidx[BB * M1 + M2 + s] = g;  outf[BB * M1 + M2 + s] = gf;
        }
    }
}

// -------------------------------------------------------------------------
// kNN (unchanged from round 13): one query per warp, lane-distributed
// sorted top-16; 2 points per lane per trip; ballots processed in
// ascending-j order with threshold re-check -> bit-exact jax top_k
// stable order. 8192 base queries; source warps also write their
// extra-region duplicate rows.
// -------------------------------------------------------------------------
#define KNN_T 256            // 8 warps = 8 queries per block
#define WPB (KNN_T / 32)
#define QTOT (BB * M1)

__global__ void __launch_bounds__(KNN_T)
knn_kernel(const float* __restrict__ pos,
           float* __restrict__ rowf, float* __restrict__ colf)
{
    const int lane = threadIdx.x & 31;
    const int wid  = threadIdx.x >> 5;
    const unsigned full = 0xffffffffu;

    const int posc = blockIdx.x * WPB + wid;      // base-region position
    const int b    = posc >> 10;                  // cloud id

    const float* __restrict__ p = pos + (size_t)b * NN * 3;

    const int qi = g_cidx[posc] & (NN - 1);
    const float qx = __ldg(&p[3 * qi + 0]);
    const float qy = __ldg(&p[3 * qi + 1]);
    const float qz = __ldg(&p[3 * qi + 2]);

    u64 mykey = ~0ull;                            // lanes 0..15: sorted list
    u64 thr   = ~0ull;                            // current list[15]

    for (int trip = 0; trip < NN / 64; ++trip) {
        const int j0 = trip * 64 + lane;
        const int j1 = j0 + 32;

        float ax = __ldg(&p[3 * j0 + 0]) - qx;
        float ay = __ldg(&p[3 * j0 + 1]) - qy;
        float az = __ldg(&p[3 * j0 + 2]) - qz;
        float bx = __ldg(&p[3 * j1 + 0]) - qx;
        float by = __ldg(&p[3 * j1 + 1]) - qy;
        float bz = __ldg(&p[3 * j1 + 2]) - qz;
        float d0 = __fadd_rn(__fadd_rn(__fmul_rn(ax, ax), __fmul_rn(ay, ay)),
                             __fmul_rn(az, az));
        float d1 = __fadd_rn(__fadd_rn(__fmul_rn(bx, bx), __fmul_rn(by, by)),
                             __fmul_rn(bz, bz));
        u64 ck0 = ((u64)__float_as_uint(d0) << 32) | (unsigned)j0;
        u64 ck1 = ((u64)__float_as_uint(d1) << 32) | (unsigned)j1;

        unsigned qm = __ballot_sync(full, ck0 < thr);
        while (qm) {
            int leader = __ffs(qm) - 1;           // lowest lane = smallest idx
            qm &= qm - 1;
            u64 cand = __shfl_sync(full, ck0, leader);
            if (cand < thr) {                     // re-check vs updated threshold
                unsigned below = __ballot_sync(full, mykey < cand) & 0xffffu;
                int pos16 = __popc(below);
                u64 up = __shfl_up_sync(full, mykey, 1);
                if (lane >= pos16) mykey = (lane == pos16) ? cand : up;
                thr = __shfl_sync(full, mykey, 15);
            }
        }
        qm = __ballot_sync(full, ck1 < thr);
        while (qm) {
            int leader = __ffs(qm) - 1;
            qm &= qm - 1;
            u64 cand = __shfl_sync(full, ck1, leader);
            if (cand < thr) {
                unsigned below = __ballot_sync(full, mykey < cand) & 0xffffu;
                int pos16 = __popc(below);
                u64 up = __shfl_up_sync(full, mykey, 1);
                if (lane >= pos16) mykey = (lane == pos16) ? cand : up;
                thr = __shfl_sync(full, mykey, 15);
            }
        }
    }

    if (lane < KNN && rowf != nullptr) {
        float cv = (float)(b * NN + (int)(unsigned)(mykey & 0xffffffffu));
        rowf[posc * KNN + lane] = (float)posc;
        colf[posc * KNN + lane] = cv;
        // Extra-region duplicate (cloud0 picks < M2; cloud1 picks < 818)
        int dst = -1;
        if (posc < M2)                                  dst = QTOT + posc;
        else if (posc >= M1 && posc < M1 + (OVSZ - M2)) dst = QTOT + M2 + (posc - M1);
        if (dst >= 0) {
            rowf[dst * KNN + lane] = (float)dst;
            colf[dst * KNN + lane] = cv;
        }
    }
}

// -------------------------------------------------------------------------
extern "C" void kernel_launch(void* const* d_in, const int* in_sizes, int n_in,
                              void* d_out, int out_size)
{
    // pos = the largest input (98304 elems; batch is 32768)
    const float* pos = (const float*)d_in[0];
    int best = -1;
    for (int i = 0; i < n_in; ++i) {
        if (in_sizes[i] > best) { best = in_sizes[i]; pos = (const float*)d_in[i]; }
    }

    float* outf = (float*)d_out;
    float* rowf = nullptr;
    float* colf = nullptr;
    if (out_size >= MTOT + 2 * MTOT * KNN) {
        rowf = outf + MTOT;
        colf = outf + MTOT + (size_t)MTOT * KNN;
    }

    static const int SMEM = NN * sizeof(float4);   // 64KB dynamic for scoords
    cudaFuncSetAttribute(fps_kernel,
                         cudaFuncAttributeMaxDynamicSharedMemorySize, SMEM);

    fps_kernel<<<BB, FPS_T, SMEM>>>(pos, outf);

    knn_kernel<<<QTOT / WPB, KNN_T>>>(pos, rowf, colf);
}

// round 15
// speedup vs baseline: 1.2502x; 1.2502x over previous
#include <cuda_runtime.h>
#include <cstdint>

// Problem constants
#define BB 8            // clouds
#define NN 4096         // points per cloud
#define M1 1024         // ceil(0.25*4096) base fps picks per cloud
#define M2 820          // ceil(0.20*4096) extra fps picks per cloud
#define OVSZ 1638       // int(8*1024*0.2) : extra picks kept
#define MTOT 9830       // BB*M1 + OVSZ
#define KNN 16

#define FPS_T 256
#define PPT 16          // points per thread (contiguous)
#define PAIRS 8

typedef unsigned long long u64;

// Internal int-valued combined indices (kNN consumes these; d_out is float32).
__device__ int g_cidx[MTOT];

// Packed f32x2 helpers (two rn.f32 ops in one instruction, bit-identical)
#define ADD2(out, a, b) asm("add.rn.f32x2 %0, %1, %2;" : "=l"(out) : "l"(a), "l"(b))
#define MUL2(out, a, b) asm("mul.rn.f32x2 %0, %1, %2;" : "=l"(out) : "l"(a), "l"(b))
#define PACK2(out, lo, hi) asm("mov.b64 %0, {%1, %2};" : "=l"(out) : "r"(lo), "r"(hi))
#define UNPK2(lo, hi, in)  asm("mov.b64 {%0, %1}, %2;" : "=r"(lo), "=r"(hi) : "l"(in))

// -------------------------------------------------------------------------
// FPS: one block per cloud, 256 threads, contiguous 16 points/thread in
// registers; winner coords from a 64KB smem float4 mirror (broadcast
// LDS.128). R13 reduction tail (ballot-prefix slot post + lane-parallel
// 2-REDUX block scan). NEW: lazy per-thread argmax --
//   inner loop tracks only bestv via fmaxf (1 FMNMX/pt instead of
//   FSETP+2SEL+FMNMX), cutting the alu-pipe load below the fma floor;
//   the index is recovered only by REDUX-tied lanes (~1-2 per warp) via
//   a descending rescan of their 16 register mind values (last match ==
//   smallest k -> identical smallest-index tie semantics; fmaxf returns
//   operand bits exactly so equality is exact).
// t==0 records winners in smem; all g_cidx/outf stores flushed at the end.
// m2 extra-fps picks are a prefix of the m1 sequence -> one pass emits all.
// -------------------------------------------------------------------------
extern __shared__ float4 scoords[];      // [NN] = 64KB dynamic

__global__ void __launch_bounds__(FPS_T, 1)
fps_kernel(const float* __restrict__ pos, float* __restrict__ outf)
{
    __shared__ alignas(16) u64 swk[2][FPS_T / 32];
    __shared__ int swin[M1];             // winner history (local indices)

    const int b    = blockIdx.x;
    const int t    = threadIdx.x;
    const int warp = t >> 5, lane = t & 31;
    const unsigned full = 0xffffffffu;

    const float* __restrict__ p = pos + (size_t)b * NN * 3;
    const int base = t * PPT;            // contiguous ownership

    u64 rx2[PAIRS], ry2[PAIRS], rz2[PAIRS];
    float mind[PPT];
#pragma unroll
    for (int m = 0; m < PAIRS; ++m) {
        int i0 = base + 2 * m;
        float x0 = p[3 * i0 + 0], y0 = p[3 * i0 + 1], z0 = p[3 * i0 + 2];
        float x1 = p[3 * i0 + 3], y1 = p[3 * i0 + 4], z1 = p[3 * i0 + 5];
        PACK2(rx2[m], __float_as_uint(x0), __float_as_uint(x1));
        PACK2(ry2[m], __float_as_uint(y0), __float_as_uint(y1));
        PACK2(rz2[m], __float_as_uint(z0), __float_as_uint(z1));
        mind[2 * m]     = __int_as_float(0x7f800000);
        mind[2 * m + 1] = __int_as_float(0x7f800000);
        scoords[i0]     = make_float4(x0, y0, z0, 0.0f);
        scoords[i0 + 1] = make_float4(x1, y1, z1, 0.0f);
    }

    if (t == 0) swin[0] = 0;             // deterministic pick 0
    __syncthreads();                     // scoords visible

    int last = 0;

    for (int s = 1; s < M1; ++s) {
        float4 c = scoords[last];        // ONE broadcast LDS.128
        unsigned nlx = __float_as_uint(-c.x);
        unsigned nly = __float_as_uint(-c.y);
        unsigned nlz = __float_as_uint(-c.z);
        u64 nlx2, nly2, nlz2;
        PACK2(nlx2, nlx, nlx);
        PACK2(nly2, nly, nly);
        PACK2(nlz2, nlz, nlz);

        float bestv = -1.0f;             // value-only running max (1 FMNMX/pt)
#pragma unroll
        for (int m = 0; m < PAIRS; ++m) {
            u64 dx2, dy2, dz2, xx2, yy2, zz2, t2, s2;
            ADD2(dx2, rx2[m], nlx2);
            ADD2(dy2, ry2[m], nly2);
            ADD2(dz2, rz2[m], nlz2);
            MUL2(xx2, dx2, dx2);
            MUL2(yy2, dy2, dy2);
            MUL2(zz2, dz2, dz2);
            ADD2(t2, xx2, yy2);
            ADD2(s2, t2, zz2);
            unsigned b0, b1;
            UNPK2(b0, b1, s2);
            float m0 = fminf(mind[2 * m],     __uint_as_float(b0));
            float m1 = fminf(mind[2 * m + 1], __uint_as_float(b1));
            mind[2 * m]     = m0;
            mind[2 * m + 1] = m1;
            bestv = fmaxf(bestv, m0);
            bestv = fmaxf(bestv, m1);
        }

        // Warp stage: one REDUX; first tied lane == min-index owner
        // (contiguous ownership: lower lane => strictly lower indices).
        // That lane lazily recovers its argmax index: descending rescan,
        // last match = smallest k.
        unsigned bv   = __float_as_uint(bestv);
        unsigned wmax = __reduce_max_sync(full, bv);
        unsigned tied = __ballot_sync(full, bv == wmax);
        if ((bv == wmax) && ((tied & ((1u << lane) - 1u)) == 0u)) {
            int besti = base;
#pragma unroll
            for (int k = PPT - 1; k >= 0; --k)
                if (mind[k] == bestv) besti = base + k;
            swk[s & 1][warp] = ((u64)wmax << 32) | (unsigned)(NN - 1 - besti);
        }
        __syncthreads();

        // Block stage: lane-parallel scan of the 8 slots (2 REDUX).
        u64 k = 0;
        if (lane < FPS_T / 32) k = swk[s & 1][lane];
        unsigned hi = (unsigned)(k >> 32);
        unsigned lo = (unsigned)k;
        unsigned m  = __reduce_max_sync(full, hi);
        unsigned cl = (hi == m) ? lo : 0u;
        unsigned wlo = __reduce_max_sync(full, cl);   // max rev-idx == min idx
        int win = NN - 1 - (int)wlo;

        if (t == 0) swin[s] = win;       // 1 STS; no global stores here
        last = win;
    }

    // Cooperative flush: all picks -> g_cidx + outf (base + extra regions).
    __syncthreads();
    for (int s = t; s < M1; s += FPS_T) {
        int g = b * NN + swin[s];
        float gf = (float)g;
        g_cidx[b * M1 + s] = g;  outf[b * M1 + s] = gf;
        if (b == 0 && s < M2) {
            g_cidx[BB * M1 + s] = g;  outf[BB * M1 + s] = gf;
        }
        if (b == 1 && s < (OVSZ - M2)) {
            g_cidx[BB * M1 + M2 + s] = g;  outf[BB * M1 + M2 + s] = gf;
        }
    }
}

// -------------------------------------------------------------------------
// kNN (unchanged from round 13): one query per warp, lane-distributed
// sorted top-16; 2 points per lane per trip; ballots processed in
// ascending-j order with threshold re-check -> bit-exact jax top_k
// stable order. 8192 base queries; source warps also write their
// extra-region duplicate rows.
// -------------------------------------------------------------------------
#define KNN_T 256            // 8 warps = 8 queries per block
#define WPB (KNN_T / 32)
#define QTOT (BB * M1)

__global__ void __launch_bounds__(KNN_T)
knn_kernel(const float* __restrict__ pos,
           float* __restrict__ rowf, float* __restrict__ colf)
{
    const int lane = threadIdx.x & 31;
    const int wid  = threadIdx.x >> 5;
    const unsigned full = 0xffffffffu;

    const int posc = blockIdx.x * WPB + wid;      // base-region position
    const int b    = posc >> 10;                  // cloud id

    const float* __restrict__ p = pos + (size_t)b * NN * 3;

    const int qi = g_cidx[posc] & (NN - 1);
    const float qx = __ldg(&p[3 * qi + 0]);
    const float qy = __ldg(&p[3 * qi + 1]);
    const float qz = __ldg(&p[3 * qi + 2]);

    u64 mykey = ~0ull;                            // lanes 0..15: sorted list
    u64 thr   = ~0ull;                            // current list[15]

    for (int trip = 0; trip < NN / 64; ++trip) {
        const int j0 = trip * 64 + lane;
        const int j1 = j0 + 32;

        float ax = __ldg(&p[3 * j0 + 0]) - qx;
        float ay = __ldg(&p[3 * j0 + 1]) - qy;
        float az = __ldg(&p[3 * j0 + 2]) - qz;
        float bx = __ldg(&p[3 * j1 + 0]) - qx;
        float by = __ldg(&p[3 * j1 + 1]) - qy;
        float bz = __ldg(&p[3 * j1 + 2]) - qz;
        float d0 = __fadd_rn(__fadd_rn(__fmul_rn(ax, ax), __fmul_rn(ay, ay)),
                             __fmul_rn(az, az));
        float d1 = __fadd_rn(__fadd_rn(__fmul_rn(bx, bx), __fmul_rn(by, by)),
                             __fmul_rn(bz, bz));
        u64 ck0 = ((u64)__float_as_uint(d0) << 32) | (unsigned)j0;
        u64 ck1 = ((u64)__float_as_uint(d1) << 32) | (unsigned)j1;

        unsigned qm = __ballot_sync(full, ck0 < thr);
        while (qm) {
            int leader = __ffs(qm) - 1;           // lowest lane = smallest idx
            qm &= qm - 1;
            u64 cand = __shfl_sync(full, ck0, leader);
            if (cand < thr) {                     // re-check vs updated threshold
                unsigned below = __ballot_sync(full, mykey < cand) & 0xffffu;
                int pos16 = __popc(below);
                u64 up = __shfl_up_sync(full, mykey, 1);
                if (lane >= pos16) mykey = (lane == pos16) ? cand : up;
                thr = __shfl_sync(full, mykey, 15);
            }
        }
        qm = __ballot_sync(full, ck1 < thr);
        while (qm) {
            int leader = __ffs(qm) - 1;
            qm &= qm - 1;
            u64 cand = __shfl_sync(full, ck1, leader);
            if (cand < thr) {
                unsigned below = __ballot_sync(full, mykey < cand) & 0xffffu;
                int pos16 = __popc(below);
                u64 up = __shfl_up_sync(full, mykey, 1);
                if (lane >= pos16) mykey = (lane == pos16) ? cand : up;
                thr = __shfl_sync(full, mykey, 15);
            }
        }
    }

    if (lane < KNN && rowf != nullptr) {
        float cv = (float)(b * NN + (int)(unsigned)(mykey & 0xffffffffu));
        rowf[posc * KNN + lane] = (float)posc;
        colf[posc * KNN + lane] = cv;
        // Extra-region duplicate (cloud0 picks < M2; cloud1 picks < 818)
        int dst = -1;
        if (posc < M2)                                  dst = QTOT + posc;
        else if (posc >= M1 && posc < M1 + (OVSZ - M2)) dst = QTOT + M2 + (posc - M1);
        if (dst >= 0) {
            rowf[dst * KNN + lane] = (float)dst;
            colf[dst * KNN + lane] = cv;
        }
    }
}

// -------------------------------------------------------------------------
extern "C" void kernel_launch(void* const* d_in, const int* in_sizes, int n_in,
                              void* d_out, int out_size)
{
    // pos = the largest input (98304 elems; batch is 32768)
    const float* pos = (const float*)d_in[0];
    int best = -1;
    for (int i = 0; i < n_in; ++i) {
        if (in_sizes[i] > best) { best = in_sizes[i]; pos = (const float*)d_in[i]; }
    }

    float* outf = (float*)d_out;
    float* rowf = nullptr;
    float* colf = nullptr;
    if (out_size >= MTOT + 2 * MTOT * KNN) {
        rowf = outf + MTOT;
        colf = outf + MTOT + (size_t)MTOT * KNN;
    }

    static const int SMEM = NN * sizeof(float4);   // 64KB dynamic for scoords
    cudaFuncSetAttribute(fps_kernel,
                         cudaFuncAttributeMaxDynamicSharedMemorySize, SMEM);

    fps_kernel<<<BB, FPS_T, SMEM>>>(pos, outf);

    knn_kernel<<<QTOT / WPB, KNN_T>>>(pos, rowf, colf);
}

// round 16
// speedup vs baseline: 1.3787x; 1.1028x over previous
#include <cuda_runtime.h>
#include <cstdint>

// Problem constants
#define BB 8            // clouds
#define NN 4096         // points per cloud
#define M1 1024         // ceil(0.25*4096) base fps picks per cloud
#define M2 820          // ceil(0.20*4096) extra fps picks per cloud
#define OVSZ 1638       // int(8*1024*0.2) : extra picks kept
#define MTOT 9830       // BB*M1 + OVSZ
#define KNN 16

#define FPS_T 256
#define PPT 16          // points per thread (contiguous)
#define PAIRS 8

typedef unsigned long long u64;

// Internal int-valued combined indices (kNN consumes these; d_out is float32).
__device__ int g_cidx[MTOT];

// Packed f32x2 helpers (two rn.f32 ops in one instruction, bit-identical)
#define ADD2(out, a, b) asm("add.rn.f32x2 %0, %1, %2;" : "=l"(out) : "l"(a), "l"(b))
#define MUL2(out, a, b) asm("mul.rn.f32x2 %0, %1, %2;" : "=l"(out) : "l"(a), "l"(b))
#define PACK2(out, lo, hi) asm("mov.b64 %0, {%1, %2};" : "=l"(out) : "r"(lo), "r"(hi))
#define UNPK2(lo, hi, in)  asm("mov.b64 {%0, %1}, %2;" : "=r"(lo), "=r"(hi) : "l"(in))

// -------------------------------------------------------------------------
// FPS (exact round-13 champion): one block per cloud, 256 threads,
// contiguous 16 points/thread in registers; winner coords from a 64KB
// smem float4 mirror (broadcast LDS.128). Per step:
//   - packed f32x2 distance + running min (exact non-FMA), per-thread
//     argmax (ascending scan, strict > -> smallest-idx ties)
//   - warp REDUX max; first tied lane posts (dist<<32)|(NN-1-idx) to a
//     parity-buffered slot; ONE barrier
//   - lane-parallel slot scan: lane<8 LDS + REDUX(dist) + REDUX(revidx
//     among tied) -- bit-identical tie-break
//   - t==0 records winner in smem history (no global stores on the
//     critical path)
// All g_cidx/outf writes flushed cooperatively at the end.
// m2 extra-fps picks are a prefix of the m1 sequence -> one pass emits all.
// -------------------------------------------------------------------------
extern __shared__ float4 scoords[];      // [NN] = 64KB dynamic

__global__ void __launch_bounds__(FPS_T, 1)
fps_kernel(const float* __restrict__ pos, float* __restrict__ outf)
{
    __shared__ alignas(16) u64 swk[2][FPS_T / 32];
    __shared__ int swin[M1];             // winner history (local indices)

    const int b    = blockIdx.x;
    const int t    = threadIdx.x;
    const int warp = t >> 5, lane = t & 31;
    const unsigned full = 0xffffffffu;

    const float* __restrict__ p = pos + (size_t)b * NN * 3;
    const int base = t * PPT;            // contiguous ownership

    u64 rx2[PAIRS], ry2[PAIRS], rz2[PAIRS];
    float mind[PPT];
#pragma unroll
    for (int m = 0; m < PAIRS; ++m) {
        int i0 = base + 2 * m;
        float x0 = p[3 * i0 + 0], y0 = p[3 * i0 + 1], z0 = p[3 * i0 + 2];
        float x1 = p[3 * i0 + 3], y1 = p[3 * i0 + 4], z1 = p[3 * i0 + 5];
        PACK2(rx2[m], __float_as_uint(x0), __float_as_uint(x1));
        PACK2(ry2[m], __float_as_uint(y0), __float_as_uint(y1));
        PACK2(rz2[m], __float_as_uint(z0), __float_as_uint(z1));
        mind[2 * m]     = __int_as_float(0x7f800000);
        mind[2 * m + 1] = __int_as_float(0x7f800000);
        scoords[i0]     = make_float4(x0, y0, z0, 0.0f);
        scoords[i0 + 1] = make_float4(x1, y1, z1, 0.0f);
    }

    if (t == 0) swin[0] = 0;             // deterministic pick 0
    __syncthreads();                     // scoords visible

    int last = 0;

    for (int s = 1; s < M1; ++s) {
        float4 c = scoords[last];        // ONE broadcast LDS.128
        unsigned nlx = __float_as_uint(-c.x);
        unsigned nly = __float_as_uint(-c.y);
        unsigned nlz = __float_as_uint(-c.z);
        u64 nlx2, nly2, nlz2;
        PACK2(nlx2, nlx, nlx);
        PACK2(nly2, nly, nly);
        PACK2(nlz2, nlz, nlz);

        float bestv = -1.0f;
        int   besti = base;
#pragma unroll
        for (int m = 0; m < PAIRS; ++m) {
            u64 dx2, dy2, dz2, xx2, yy2, zz2, t2, s2;
            ADD2(dx2, rx2[m], nlx2);
            ADD2(dy2, ry2[m], nly2);
            ADD2(dz2, rz2[m], nlz2);
            MUL2(xx2, dx2, dx2);
            MUL2(yy2, dy2, dy2);
            MUL2(zz2, dz2, dz2);
            ADD2(t2, xx2, yy2);
            ADD2(s2, t2, zz2);
            unsigned b0, b1;
            UNPK2(b0, b1, s2);
            float m0 = fminf(mind[2 * m],     __uint_as_float(b0));
            float m1 = fminf(mind[2 * m + 1], __uint_as_float(b1));
            mind[2 * m]     = m0;
            mind[2 * m + 1] = m1;
            // ascending idx + strict > keeps smallest idx on tie
            if (m0 > bestv) { bestv = m0; besti = base + 2 * m;     }
            if (m1 > bestv) { bestv = m1; besti = base + 2 * m + 1; }
        }

        // Warp stage: one REDUX; first tied lane == min-index owner
        // (contiguous ownership: lower lane => strictly lower indices).
        unsigned bv   = __float_as_uint(bestv);
        unsigned wmax = __reduce_max_sync(full, bv);
        unsigned tied = __ballot_sync(full, bv == wmax);
        if ((bv == wmax) && ((tied & ((1u << lane) - 1u)) == 0u)) {
            swk[s & 1][warp] = ((u64)wmax << 32) | (unsigned)(NN - 1 - besti);
        }
        __syncthreads();

        // Block stage: lane-parallel scan of the 8 slots (2 REDUX).
        u64 k = 0;
        if (lane < FPS_T / 32) k = swk[s & 1][lane];
        unsigned hi = (unsigned)(k >> 32);
        unsigned lo = (unsigned)k;
        unsigned m  = __reduce_max_sync(full, hi);
        unsigned cl = (hi == m) ? lo : 0u;
        unsigned wlo = __reduce_max_sync(full, cl);   // max rev-idx == min idx
        int win = NN - 1 - (int)wlo;

        if (t == 0) swin[s] = win;       // 1 STS; no global stores here
        last = win;
    }

    // Cooperative flush: all picks -> g_cidx + outf (base + extra regions).
    __syncthreads();
    for (int s = t; s < M1; s += FPS_T) {
        int g = b * NN + swin[s];
        float gf = (float)g;
        g_cidx[b * M1 + s] = g;  outf[b * M1 + s] = gf;
        if (b == 0 && s < M2) {
            g_cidx[BB * M1 + s] = g;  outf[BB * M1 + s] = gf;
        }
        if (b == 1 && s < (OVSZ - M2)) {
            g_cidx[BB * M1 + M2 + s] = g;  outf[BB * M1 + M2 + s] = gf;
        }
    }
}

// -------------------------------------------------------------------------
// kNN: one query per warp, lane-distributed sorted top-16; 2 points per
// lane per trip; ballots in ascending-j order with exact u64 re-check
// inside the insert loop -> bit-exact jax top_k stable order.
// NEW: ballot precondition uses a float threshold (d <= thr_f), a strict
// SUPERSET of the exact u64 test (ties on dist are kept); the exact
// `cand < thr` re-check rejects any false positive, so selection is
// bit-identical while the hot path drops the 64-bit compare.
// 8192 base queries; source warps also write extra-region duplicates.
// -------------------------------------------------------------------------
#define KNN_T 256            // 8 warps = 8 queries per block
#define WPB (KNN_T / 32)
#define QTOT (BB * M1)

__global__ void __launch_bounds__(KNN_T)
knn_kernel(const float* __restrict__ pos,
           float* __restrict__ rowf, float* __restrict__ colf)
{
    const int lane = threadIdx.x & 31;
    const int wid  = threadIdx.x >> 5;
    const unsigned full = 0xffffffffu;

    const int posc = blockIdx.x * WPB + wid;      // base-region position
    const int b    = posc >> 10;                  // cloud id

    const float* __restrict__ p = pos + (size_t)b * NN * 3;

    const int qi = g_cidx[posc] & (NN - 1);
    const float qx = __ldg(&p[3 * qi + 0]);
    const float qy = __ldg(&p[3 * qi + 1]);
    const float qz = __ldg(&p[3 * qi + 2]);

    u64   mykey = ~0ull;                          // lanes 0..15: sorted list
    u64   thr   = ~0ull;                          // exact threshold (list[15])
    float thr_f = __int_as_float(0x7f800000);     // +inf: superset of ~0ull dist

    for (int trip = 0; trip < NN / 64; ++trip) {
        const int j0 = trip * 64 + lane;
        const int j1 = j0 + 32;

        float ax = __ldg(&p[3 * j0 + 0]) - qx;
        float ay = __ldg(&p[3 * j0 + 1]) - qy;
        float az = __ldg(&p[3 * j0 + 2]) - qz;
        float bx = __ldg(&p[3 * j1 + 0]) - qx;
        float by = __ldg(&p[3 * j1 + 1]) - qy;
        float bz = __ldg(&p[3 * j1 + 2]) - qz;
        float d0 = __fadd_rn(__fadd_rn(__fmul_rn(ax, ax), __fmul_rn(ay, ay)),
                             __fmul_rn(az, az));
        float d1 = __fadd_rn(__fadd_rn(__fmul_rn(bx, bx), __fmul_rn(by, by)),
                             __fmul_rn(bz, bz));
        u64 ck0 = ((u64)__float_as_uint(d0) << 32) | (unsigned)j0;
        u64 ck1 = ((u64)__float_as_uint(d1) << 32) | (unsigned)j1;

        unsigned qm = __ballot_sync(full, d0 <= thr_f);   // superset filter
        while (qm) {
            int leader = __ffs(qm) - 1;           // lowest lane = smallest idx
            qm &= qm - 1;
            u64 cand = __shfl_sync(full, ck0, leader);
            if (cand < thr) {                     // EXACT check (u64)
                unsigned below = __ballot_sync(full, mykey < cand) & 0xffffu;
                int pos16 = __popc(below);
                u64 up = __shfl_up_sync(full, mykey, 1);
                if (lane >= pos16) mykey = (lane == pos16) ? cand : up;
                thr = __shfl_sync(full, mykey, 15);
                thr_f = __uint_as_float((unsigned)(thr >> 32));
            }
        }
        qm = __ballot_sync(full, d1 <= thr_f);
        while (qm) {
            int leader = __ffs(qm) - 1;
            qm &= qm - 1;
            u64 cand = __shfl_sync(full, ck1, leader);
            if (cand < thr) {
                unsigned below = __ballot_sync(full, mykey < cand) & 0xffffu;
                int pos16 = __popc(below);
                u64 up = __shfl_up_sync(full, mykey, 1);
                if (lane >= pos16) mykey = (lane == pos16) ? cand : up;
                thr = __shfl_sync(full, mykey, 15);
                thr_f = __uint_as_float((unsigned)(thr >> 32));
            }
        }
    }

    if (lane < KNN && rowf != nullptr) {
        float cv = (float)(b * NN + (int)(unsigned)(mykey & 0xffffffffu));
        rowf[posc * KNN + lane] = (float)posc;
        colf[posc * KNN + lane] = cv;
        // Extra-region duplicate (cloud0 picks < M2; cloud1 picks < 818)
        int dst = -1;
        if (posc < M2)                                  dst = QTOT + posc;
        else if (posc >= M1 && posc < M1 + (OVSZ - M2)) dst = QTOT + M2 + (posc - M1);
        if (dst >= 0) {
            rowf[dst * KNN + lane] = (float)dst;
            colf[dst * KNN + lane] = cv;
        }
    }
}

// -------------------------------------------------------------------------
extern "C" void kernel_launch(void* const* d_in, const int* in_sizes, int n_in,
                              void* d_out, int out_size)
{
    // pos = the largest input (98304 elems; batch is 32768)
    const float* pos = (const float*)d_in[0];
    int best = -1;
    for (int i = 0; i < n_in; ++i) {
        if (in_sizes[i] > best) { best = in_sizes[i]; pos = (const float*)d_in[i]; }
    }

    float* outf = (float*)d_out;
    float* rowf = nullptr;
    float* colf = nullptr;
    if (out_size >= MTOT + 2 * MTOT * KNN) {
        rowf = outf + MTOT;
        colf = outf + MTOT + (size_t)MTOT * KNN;
    }

    static const int SMEM = NN * sizeof(float4);   // 64KB dynamic for scoords
    cudaFuncSetAttribute(fps_kernel,
                         cudaFuncAttributeMaxDynamicSharedMemorySize, SMEM);

    fps_kernel<<<BB, FPS_T, SMEM>>>(pos, outf);

    knn_kernel<<<QTOT / WPB, KNN_T>>>(pos, rowf, colf);
}